// round 10
// baseline (speedup 1.0000x reference)
#include <cuda_runtime.h>
#include <math.h>

#define Nn 1024
#define C1 384
#define C2 128
#define Hh 12
#define FEATD 2112
#define NCHd 384
#define PW 1152
#define LPAD 20

// ---------------- scratch (device globals; no runtime allocation) ----------------
static __device__ float g_P[Nn * PW];               // projections (1024x1152)
static __device__ float g_qpt[Nn * Hh * 12];        // global q points (n,h,p*3+i)
static __device__ float g_kpt[Nn * Hh * 12];
static __device__ float g_vpt[Nn * Hh * 24];
static __device__ float g_qn[Nn * Hh];              // |q_pts|^2 per (n,h)
static __device__ float g_kn[Nn * Hh];
static __device__ float g_bufA[(size_t)Hh * Nn * Nn]; // (h,q,k): cheap logits, then attn
static __device__ float g_out6[Nn * Hh * 40];       // [v_scalar(16) | point(24)] per (q,h)
static __device__ float g_feat[Nn * FEATD];         // assembled feature rows

// packed fp32x2 FMA: d0 += a0*b0 ; d1 += a1*b1
__device__ __forceinline__ void ffma2(float& d0, float& d1, float a0, float a1,
                                      float b0, float b1) {
    asm("{\n\t"
        ".reg .b64 ra, rb, rc;\n\t"
        "mov.b64 ra, {%2, %3};\n\t"
        "mov.b64 rb, {%4, %5};\n\t"
        "mov.b64 rc, {%0, %1};\n\t"
        "fma.rn.f32x2 rc, ra, rb, rc;\n\t"
        "mov.b64 {%0, %1}, rc;\n\t"
        "}"
        : "+f"(d0), "+f"(d1)
        : "f"(a0), "f"(a1), "f"(b0), "f"(b1));
}

// source of the assembled projection matrix column `col`, row `c`
__device__ __forceinline__ float wsrc(const float* __restrict__ wqp, const float* __restrict__ wkp,
                                      const float* __restrict__ wvp, const float* __restrict__ wqs,
                                      const float* __restrict__ wks, const float* __restrict__ wvs,
                                      int c, int col) {
    if (col < 144)  return wqp[c * 144 + col];
    if (col < 288)  return wkp[c * 144 + col - 144];
    if (col < 576)  return wvp[c * 288 + col - 288];
    if (col < 768)  return wqs[c * 192 + col - 576];
    if (col < 960)  return wks[c * 192 + col - 768];
    return wvs[c * 192 + col - 960];
}

// ---------------- K1: projection GEMM 1024x1152x384 (weights assembled on the fly) ----------------
__global__ __launch_bounds__(256) void k_proj(const float* __restrict__ A,
                                              const float* __restrict__ wqp, const float* __restrict__ wkp,
                                              const float* __restrict__ wvp, const float* __restrict__ wqs,
                                              const float* __restrict__ wks, const float* __restrict__ wvs,
                                              const float* __restrict__ bqp, const float* __restrict__ bkp,
                                              const float* __restrict__ bvp) {
    __shared__ __align__(16) float As[16 * 64];
    __shared__ __align__(16) float Bs[16 * 64];
    int n0 = blockIdx.x * 64, m0 = blockIdx.y * 64;
    int t = threadIdx.x;
    int tx = t & 15, ty = t >> 4;
    float acc[4][4] = {};
    for (int kc = 0; kc < C1; kc += 16) {
#pragma unroll
        for (int r = 0; r < 4; r++) {
            int idx = t + r * 256;
            As[(idx & 15) * 64 + (idx >> 4)] = A[(m0 + (idx >> 4)) * C1 + kc + (idx & 15)];
            Bs[(idx >> 6) * 64 + (idx & 63)] =
                wsrc(wqp, wkp, wvp, wqs, wks, wvs, kc + (idx >> 6), n0 + (idx & 63));
        }
        __syncthreads();
#pragma unroll
        for (int kk = 0; kk < 16; kk++) {
            float4 a4 = *(const float4*)(As + kk * 64 + ty * 4);
            float4 b4 = *(const float4*)(Bs + kk * 64 + tx * 4);
            ffma2(acc[0][0], acc[0][1], a4.x, a4.x, b4.x, b4.y);
            ffma2(acc[0][2], acc[0][3], a4.x, a4.x, b4.z, b4.w);
            ffma2(acc[1][0], acc[1][1], a4.y, a4.y, b4.x, b4.y);
            ffma2(acc[1][2], acc[1][3], a4.y, a4.y, b4.z, b4.w);
            ffma2(acc[2][0], acc[2][1], a4.z, a4.z, b4.x, b4.y);
            ffma2(acc[2][2], acc[2][3], a4.z, a4.z, b4.z, b4.w);
            ffma2(acc[3][0], acc[3][1], a4.w, a4.w, b4.x, b4.y);
            ffma2(acc[3][2], acc[3][3], a4.w, a4.w, b4.z, b4.w);
        }
        __syncthreads();
    }
#pragma unroll
    for (int i = 0; i < 4; i++) {
        int m = m0 + ty * 4 + i;
#pragma unroll
        for (int j = 0; j < 4; j++) {
            int n = n0 + tx * 4 + j;
            float b = 0.f;
            if (n < 144)      b = bqp[n];
            else if (n < 288) b = bkp[n - 144];
            else if (n < 576) b = bvp[n - 288];
            float s = (n >= 576 && n < 768) ? 0.25f : 1.f;   // q_scalar * sqrt(1/16)
            g_P[m * PW + n] = acc[i][j] * s + b;
        }
    }
}

// ---------------- K2: rigid transform + point norms ----------------
__global__ void k_rotate(const float* __restrict__ rot, const float* __restrict__ trans) {
    int n = blockIdx.x;
    int t = threadIdx.x;
    __shared__ float R[9], T[3];
    if (t < 9) R[t] = rot[n * 9 + t];
    if (t < 3) T[t] = trans[n * 3 + t];
    __syncthreads();
    if (t < 192) {
        float l0, l1, l2;
        float* dst;
        if (t < 48) {
            int h = t >> 2, p = t & 3;
            const float* src = &g_P[n * PW + h * 12];
            l0 = src[p]; l1 = src[4 + p]; l2 = src[8 + p];
            dst = &g_qpt[(n * 12 + h) * 12 + p * 3];
        } else if (t < 96) {
            int u = t - 48; int h = u >> 2, p = u & 3;
            const float* src = &g_P[n * PW + 144 + h * 12];
            l0 = src[p]; l1 = src[4 + p]; l2 = src[8 + p];
            dst = &g_kpt[(n * 12 + h) * 12 + p * 3];
        } else {
            int u = t - 96; int h = u >> 3, p = u & 7;
            const float* src = &g_P[n * PW + 288 + h * 24];
            l0 = src[p]; l1 = src[8 + p]; l2 = src[16 + p];
            dst = &g_vpt[(n * 12 + h) * 24 + p * 3];
        }
        dst[0] = R[0] * l0 + R[1] * l1 + R[2] * l2 + T[0];
        dst[1] = R[3] * l0 + R[4] * l1 + R[5] * l2 + T[1];
        dst[2] = R[6] * l0 + R[7] * l1 + R[8] * l2 + T[2];
    }
    __syncthreads();
    if (t < 24) {
        int h = t % 12;
        const float* p = (t < 12) ? &g_qpt[(n * 12 + h) * 12] : &g_kpt[(n * 12 + h) * 12];
        float s = 0.f;
#pragma unroll
        for (int d = 0; d < 12; d++) s += p[d] * p[d];
        if (t < 12) g_qn[n * 12 + h] = s;
        else        g_kn[n * 12 + h] = s;
    }
}

// ---------------- K3: cheap logits (scalar QK + point + b2d) -> (h,q,k), 128x64 tiles ----------------
__global__ __launch_bounds__(256) void k_cheap(const float* __restrict__ b2d,
                                               const float* __restrict__ rawpw) {
    int k0 = blockIdx.x * 64, q0 = blockIdx.y * 128, h = blockIdx.z;
    __shared__ __align__(16) float qf[28 * 128];   // [c][r]
    __shared__ __align__(16) float kf[28 * 64];
    __shared__ float qn_[128], kn_[64];
    int t = threadIdx.x;
    float x = rawpw[h];
    float sp = (x > 20.f) ? x : log1pf(expf(x));
    float pw = sqrtf(1.f / 18.f) * sp;             // point_var = 4*9/2 = 18
    // fill q-features (128 rows x 7 float4 groups)
    for (int u = t; u < 1024; u += 256) {
        int r = u >> 3, g = u & 7;
        if (g < 4) {
            float4 v = *(const float4*)(&g_P[(size_t)(q0 + r) * PW + 576 + h * 16 + g * 4]);
            qf[(g * 4 + 0) * 128 + r] = v.x; qf[(g * 4 + 1) * 128 + r] = v.y;
            qf[(g * 4 + 2) * 128 + r] = v.z; qf[(g * 4 + 3) * 128 + r] = v.w;
        } else if (g < 7) {
            int pc = 16 + (g - 4) * 4;
            float4 v = *(const float4*)(&g_qpt[(((size_t)(q0 + r)) * 12 + h) * 12 + (g - 4) * 4]);
            qf[(pc + 0) * 128 + r] = v.x; qf[(pc + 1) * 128 + r] = v.y;
            qf[(pc + 2) * 128 + r] = v.z; qf[(pc + 3) * 128 + r] = v.w;
        }
    }
    // fill k-features (64 rows x 7 groups), point part pre-scaled by pw
    for (int u = t; u < 512; u += 256) {
        int r = u >> 3, g = u & 7;
        if (g < 4) {
            float4 w = *(const float4*)(&g_P[(size_t)(k0 + r) * PW + 768 + h * 16 + g * 4]);
            kf[(g * 4 + 0) * 64 + r] = w.x; kf[(g * 4 + 1) * 64 + r] = w.y;
            kf[(g * 4 + 2) * 64 + r] = w.z; kf[(g * 4 + 3) * 64 + r] = w.w;
        } else if (g < 7) {
            int pc = 16 + (g - 4) * 4;
            float4 w = *(const float4*)(&g_kpt[(((size_t)(k0 + r)) * 12 + h) * 12 + (g - 4) * 4]);
            kf[(pc + 0) * 64 + r] = pw * w.x; kf[(pc + 1) * 64 + r] = pw * w.y;
            kf[(pc + 2) * 64 + r] = pw * w.z; kf[(pc + 3) * 64 + r] = pw * w.w;
        }
    }
    if (t < 128)           qn_[t] = 0.5f * pw * g_qn[(q0 + t) * 12 + h];
    else if (t < 192)      kn_[t - 128] = 0.5f * pw * g_kn[(k0 + t - 128) * 12 + h];
    __syncthreads();
    int tx = t & 15, ty = t >> 4;
    float acc[8][4] = {};
#pragma unroll
    for (int c = 0; c < 28; c++) {
        float4 aA = *(const float4*)(qf + c * 128 + ty * 8);
        float4 aB = *(const float4*)(qf + c * 128 + ty * 8 + 4);
        float4 b4 = *(const float4*)(kf + c * 64 + tx * 4);
        ffma2(acc[0][0], acc[0][1], aA.x, aA.x, b4.x, b4.y);
        ffma2(acc[0][2], acc[0][3], aA.x, aA.x, b4.z, b4.w);
        ffma2(acc[1][0], acc[1][1], aA.y, aA.y, b4.x, b4.y);
        ffma2(acc[1][2], acc[1][3], aA.y, aA.y, b4.z, b4.w);
        ffma2(acc[2][0], acc[2][1], aA.z, aA.z, b4.x, b4.y);
        ffma2(acc[2][2], acc[2][3], aA.z, aA.z, b4.z, b4.w);
        ffma2(acc[3][0], acc[3][1], aA.w, aA.w, b4.x, b4.y);
        ffma2(acc[3][2], acc[3][3], aA.w, aA.w, b4.z, b4.w);
        ffma2(acc[4][0], acc[4][1], aB.x, aB.x, b4.x, b4.y);
        ffma2(acc[4][2], acc[4][3], aB.x, aB.x, b4.z, b4.w);
        ffma2(acc[5][0], acc[5][1], aB.y, aB.y, b4.x, b4.y);
        ffma2(acc[5][2], acc[5][3], aB.y, aB.y, b4.z, b4.w);
        ffma2(acc[6][0], acc[6][1], aB.z, aB.z, b4.x, b4.y);
        ffma2(acc[6][2], acc[6][3], aB.z, aB.z, b4.z, b4.w);
        ffma2(acc[7][0], acc[7][1], aB.w, aB.w, b4.x, b4.y);
        ffma2(acc[7][2], acc[7][3], aB.w, aB.w, b4.z, b4.w);
    }
    float bb = b2d[h];
#pragma unroll
    for (int i = 0; i < 8; i++) {
        int q = q0 + ty * 8 + i;
#pragma unroll
        for (int j = 0; j < 4; j++) {
            int k = k0 + tx * 4 + j;
            g_bufA[((size_t)h << 20) + (size_t)q * 1024 + k] =
                acc[i][j] - qn_[ty * 8 + i] - kn_[tx * 4 + j] + bb;
        }
    }
}

// ---------------- K4: fused inputs_2d projection + cheap-add + mask + softmax ----------------
// one block per q; thread t owns k in {t, t+256, t+512, t+768}; attn -> g_bufA (h,q,k)
__global__ __launch_bounds__(256) void k_logits(const float* __restrict__ in2d,
                                                const float* __restrict__ w2d,
                                                const float* __restrict__ mask) {
    extern __shared__ float dsm[];
    float* s2d = dsm;                 // [1024][LPAD]
    float* ws  = dsm + 1024 * LPAD;   // 192 floats (w2d chunk); reused as red[96]
    int q = blockIdx.x, t = threadIdx.x;
    float acc[4][12];
#pragma unroll
    for (int s = 0; s < 4; s++)
#pragma unroll
        for (int h = 0; h < 12; h++) acc[s][h] = 0.f;
    const float* inrow = in2d + (size_t)q * 131072;
    for (int c0 = 0; c0 < 128; c0 += 16) {
        if (t < 192) ws[t] = w2d[c0 * 12 + t];
#pragma unroll
        for (int it = 0; it < 16; it++) {
            int idx = t + it * 256;
            int row = idx >> 2, cq = (idx & 3) * 4;
            float4 v = *(const float4*)(inrow + row * 128 + c0 + cq);
            *(float4*)(s2d + row * LPAD + cq) = v;
        }
        __syncthreads();
#pragma unroll
        for (int c4 = 0; c4 < 4; c4++) {
            float4 a[4];
#pragma unroll
            for (int s = 0; s < 4; s++)
                a[s] = *(const float4*)(s2d + (t + s * 256) * LPAD + c4 * 4);
#pragma unroll
            for (int cc = 0; cc < 4; cc++) {
                const float* wb = ws + (c4 * 4 + cc) * 12;
                float4 b0 = *(const float4*)(wb);
                float4 b1 = *(const float4*)(wb + 4);
                float4 b2 = *(const float4*)(wb + 8);
#pragma unroll
                for (int s = 0; s < 4; s++) {
                    float av = (cc == 0) ? a[s].x : (cc == 1) ? a[s].y
                             : (cc == 2) ? a[s].z : a[s].w;
                    ffma2(acc[s][0],  acc[s][1],  av, av, b0.x, b0.y);
                    ffma2(acc[s][2],  acc[s][3],  av, av, b0.z, b0.w);
                    ffma2(acc[s][4],  acc[s][5],  av, av, b1.x, b1.y);
                    ffma2(acc[s][6],  acc[s][7],  av, av, b1.z, b1.w);
                    ffma2(acc[s][8],  acc[s][9],  av, av, b2.x, b2.y);
                    ffma2(acc[s][10], acc[s][11], av, av, b2.z, b2.w);
                }
            }
        }
        __syncthreads();
    }
    // ---- epilogue: add cheap, mask, scale ----
    float* red = ws;
    const float scale = 0.57735026918962576f;
    float mq = mask[q];
    float pen[4];
#pragma unroll
    for (int s = 0; s < 4; s++) pen[s] = -1e5f * (1.f - mq * mask[t + s * 256]);
#pragma unroll
    for (int h = 0; h < 12; h++) {
        size_t off = ((size_t)h << 20) + ((size_t)q << 10) + t;
#pragma unroll
        for (int s = 0; s < 4; s++) {
            float ch = g_bufA[off + s * 256];
            acc[s][h] = (acc[s][h] + ch + pen[s]) * scale;
        }
    }
    // ---- softmax over k (block-wide per h) ----
    int w = t >> 5, lane = t & 31;
#pragma unroll
    for (int h = 0; h < 12; h++) {
        float m = fmaxf(fmaxf(acc[0][h], acc[1][h]), fmaxf(acc[2][h], acc[3][h]));
#pragma unroll
        for (int s = 16; s; s >>= 1) m = fmaxf(m, __shfl_xor_sync(0xffffffffu, m, s));
        if (lane == 0) red[w * 12 + h] = m;
    }
    __syncthreads();
    float hm[12];
#pragma unroll
    for (int h = 0; h < 12; h++) {
        float m = red[h];
#pragma unroll
        for (int w2 = 1; w2 < 8; w2++) m = fmaxf(m, red[w2 * 12 + h]);
        hm[h] = m;
    }
    __syncthreads();
#pragma unroll
    for (int h = 0; h < 12; h++) {
        float s0 = 0.f;
#pragma unroll
        for (int s = 0; s < 4; s++) {
            acc[s][h] = __expf(acc[s][h] - hm[h]);
            s0 += acc[s][h];
        }
#pragma unroll
        for (int s = 16; s; s >>= 1) s0 += __shfl_xor_sync(0xffffffffu, s0, s);
        if (lane == 0) red[w * 12 + h] = s0;
    }
    __syncthreads();
#pragma unroll
    for (int h = 0; h < 12; h++) {
        float tot = red[h];
#pragma unroll
        for (int w2 = 1; w2 < 8; w2++) tot += red[w2 * 12 + h];
        float inv = 1.f / tot;
        size_t off = ((size_t)h << 20) + ((size_t)q << 10) + t;
#pragma unroll
        for (int s = 0; s < 4; s++) g_bufA[off + s * 256] = acc[s][h] * inv;
    }
}

// ---------------- K5: AV (scalar + point values), per-head GEMM ----------------
__global__ __launch_bounds__(256) void k_av() {
    __shared__ __align__(16) float As[64 * 64];   // [kk][r]
    __shared__ float Bs[64 * 48];
    int h = blockIdx.y;
    int q0 = blockIdx.x * 64;
    int t = threadIdx.x;
    int tx = t & 15, ty = t >> 4;
    float acc[4][3] = {};
    for (int k0 = 0; k0 < 1024; k0 += 64) {
        const float* ab = g_bufA + ((size_t)h << 20) + (size_t)q0 * 1024 + k0;
        for (int idx = t; idx < 1024; idx += 256) {
            int r = idx >> 4, c4 = (idx & 15) * 4;
            float4 v = *(const float4*)(ab + (size_t)r * 1024 + c4);
            As[(c4 + 0) * 64 + r] = v.x; As[(c4 + 1) * 64 + r] = v.y;
            As[(c4 + 2) * 64 + r] = v.z; As[(c4 + 3) * 64 + r] = v.w;
        }
        for (int idx = t; idx < 64 * 48; idx += 256) {
            int kk = idx / 48, col = idx - kk * 48;
            int k = k0 + kk;
            float v = 0.f;
            if (col < 16)       v = g_P[(size_t)k * 1152 + 960 + h * 16 + col];
            else if (col < 40)  v = g_vpt[((size_t)k * 12 + h) * 24 + (col - 16)];
            Bs[kk * 48 + col] = v;
        }
        __syncthreads();
#pragma unroll 8
        for (int kk = 0; kk < 64; kk++) {
            float4 a4 = *(const float4*)(As + kk * 64 + ty * 4);
            float b0 = Bs[kk * 48 + tx * 3 + 0];
            float b1 = Bs[kk * 48 + tx * 3 + 1];
            float b2 = Bs[kk * 48 + tx * 3 + 2];
            ffma2(acc[0][0], acc[1][0], a4.x, a4.y, b0, b0);
            ffma2(acc[2][0], acc[3][0], a4.z, a4.w, b0, b0);
            ffma2(acc[0][1], acc[1][1], a4.x, a4.y, b1, b1);
            ffma2(acc[2][1], acc[3][1], a4.z, a4.w, b1, b1);
            ffma2(acc[0][2], acc[1][2], a4.x, a4.y, b2, b2);
            ffma2(acc[2][2], acc[3][2], a4.z, a4.w, b2, b2);
        }
        __syncthreads();
    }
#pragma unroll
    for (int i = 0; i < 4; i++) {
        int q = q0 + ty * 4 + i;
#pragma unroll
        for (int j = 0; j < 3; j++) {
            int col = tx * 3 + j;
            if (col < 40) g_out6[((size_t)q * 12 + h) * 40 + col] = acc[i][j];
        }
    }
}

// ---------------- K6: res_2d per q (second in2d pass) ----------------
// 256 threads = 64 c-pairs x 4 k-slices; dynamic smem 12288 floats (attn planes)
__global__ __launch_bounds__(256) void k_final(const float* __restrict__ in2d) {
    extern __shared__ float sa[];   // [h][1024]
    int q = blockIdx.x;
    int t = threadIdx.x;
#pragma unroll
    for (int h = 0; h < 12; h++) {
        float4 v = *(const float4*)(g_bufA + ((size_t)h << 20) + ((size_t)q << 10) + t * 4);
        *(float4*)(sa + h * 1024 + t * 4) = v;
    }
    __syncthreads();
    int cp = t & 63, ks = t >> 6;
    float aX[12], aY[12];
#pragma unroll
    for (int u = 0; u < 12; u++) { aX[u] = 0.f; aY[u] = 0.f; }
    const float* base = in2d + (size_t)q * 131072 + cp * 2;
    int kbase = ks * 256;
    for (int kt = 0; kt < 64; kt++) {
        int k0 = kbase + kt * 4;
        float2 v0 = *(const float2*)(base + (size_t)(k0 + 0) * 128);
        float2 v1 = *(const float2*)(base + (size_t)(k0 + 1) * 128);
        float2 v2 = *(const float2*)(base + (size_t)(k0 + 2) * 128);
        float2 v3 = *(const float2*)(base + (size_t)(k0 + 3) * 128);
#pragma unroll
        for (int u = 0; u < 6; u++) {
            float4 a0 = *(const float4*)(sa + (2 * u) * 1024 + k0);
            float4 a1 = *(const float4*)(sa + (2 * u + 1) * 1024 + k0);
            ffma2(aX[2 * u], aX[2 * u + 1], a0.x, a1.x, v0.x, v0.x);
            ffma2(aY[2 * u], aY[2 * u + 1], a0.x, a1.x, v0.y, v0.y);
            ffma2(aX[2 * u], aX[2 * u + 1], a0.y, a1.y, v1.x, v1.x);
            ffma2(aY[2 * u], aY[2 * u + 1], a0.y, a1.y, v1.y, v1.y);
            ffma2(aX[2 * u], aX[2 * u + 1], a0.z, a1.z, v2.x, v2.x);
            ffma2(aY[2 * u], aY[2 * u + 1], a0.z, a1.z, v2.y, v2.y);
            ffma2(aX[2 * u], aX[2 * u + 1], a0.w, a1.w, v3.x, v3.x);
            ffma2(aY[2 * u], aY[2 * u + 1], a0.w, a1.w, v3.y, v3.y);
        }
    }
    __syncthreads();   // everyone done reading attn from sa
    if (ks != 0) {
        float* d = sa + (size_t)((ks - 1) * 64 + cp) * 24;
#pragma unroll
        for (int u = 0; u < 12; u++) { d[u] = aX[u]; d[12 + u] = aY[u]; }
    }
    __syncthreads();
    if (ks == 0) {
#pragma unroll
        for (int s = 0; s < 3; s++) {
            const float* d = sa + (size_t)(s * 64 + cp) * 24;
#pragma unroll
            for (int u = 0; u < 12; u++) { aX[u] += d[u]; aY[u] += d[12 + u]; }
        }
        float* f = g_feat + (size_t)q * 2112 + 576;
#pragma unroll
        for (int hh = 0; hh < 12; hh++) {
            f[hh * 128 + 2 * cp]     = aX[hh];
            f[hh * 128 + 2 * cp + 1] = aY[hh];
        }
    }
}

// ---------------- K7: inverse rigid, norms, feature assembly ----------------
__global__ void k_post(const float* __restrict__ rot, const float* __restrict__ trans) {
    int q = blockIdx.x;
    int t = threadIdx.x;   // 288
    float* f = g_feat + (size_t)q * 2112;
    const float* o6 = g_out6 + (size_t)q * 12 * 40;
    if (t < 96) {
        int h = t >> 3, p = t & 7;
        const float* g = o6 + h * 40 + 16 + p * 3;
        float g0 = g[0] - trans[q * 3 + 0];
        float g1 = g[1] - trans[q * 3 + 1];
        float g2 = g[2] - trans[q * 3 + 2];
        const float* R = rot + q * 9;
        float l0 = R[0] * g0 + R[3] * g1 + R[6] * g2;
        float l1 = R[1] * g0 + R[4] * g1 + R[7] * g2;
        float l2 = R[2] * g0 + R[5] * g1 + R[8] * g2;
        int idx = h * 8 + p;
        f[192 + idx] = l0;
        f[288 + idx] = l1;
        f[384 + idx] = l2;
        f[480 + idx] = sqrtf(fmaxf(l0 * l0 + l1 * l1 + l2 * l2, 1e-16f));
    } else if (t < 288) {
        int idx = t - 96;           // 0..191
        int h = idx >> 4, s = idx & 15;
        f[idx] = o6[h * 40 + s];
    }
}

// ---------------- K8: output GEMM 1024x384x2112 (32x64 tiles) ----------------
__global__ __launch_bounds__(256) void k_out(const float* __restrict__ wout,
                                             const float* __restrict__ bout,
                                             float* __restrict__ out) {
    __shared__ __align__(16) float As[16 * 32];
    __shared__ __align__(16) float Bs[16 * 64];
    int n0 = blockIdx.x * 64, m0 = blockIdx.y * 32;
    int t = threadIdx.x;
    int tx = t & 15, ty = t >> 4;
    float acc[2][4] = {};
    for (int kc = 0; kc < FEATD; kc += 16) {
#pragma unroll
        for (int r = 0; r < 2; r++) {
            int idx = t + r * 256;
            As[(idx & 15) * 32 + (idx >> 4)] =
                g_feat[(size_t)(m0 + (idx >> 4)) * FEATD + kc + (idx & 15)];
        }
#pragma unroll
        for (int r = 0; r < 4; r++) {
            int idx = t + r * 256;
            Bs[(idx >> 6) * 64 + (idx & 63)] =
                wout[(size_t)(kc + (idx >> 6)) * NCHd + n0 + (idx & 63)];
        }
        __syncthreads();
#pragma unroll
        for (int kk = 0; kk < 16; kk++) {
            float2 a2 = *(const float2*)(As + kk * 32 + ty * 2);
            float4 b4 = *(const float4*)(Bs + kk * 64 + tx * 4);
            ffma2(acc[0][0], acc[0][1], a2.x, a2.x, b4.x, b4.y);
            ffma2(acc[0][2], acc[0][3], a2.x, a2.x, b4.z, b4.w);
            ffma2(acc[1][0], acc[1][1], a2.y, a2.y, b4.x, b4.y);
            ffma2(acc[1][2], acc[1][3], a2.y, a2.y, b4.z, b4.w);
        }
        __syncthreads();
    }
#pragma unroll
    for (int i = 0; i < 2; i++) {
        int m = m0 + ty * 2 + i;
#pragma unroll
        for (int j = 0; j < 4; j++) {
            int n = n0 + tx * 4 + j;
            out[(size_t)m * NCHd + n] = acc[i][j] + bout[n];
        }
    }
}

// ---------------- launch ----------------
extern "C" void kernel_launch(void* const* d_in, const int* in_sizes, int n_in,
                              void* d_out, int out_size) {
    const float* inputs_1d = (const float*)d_in[0];
    const float* inputs_2d = (const float*)d_in[1];
    const float* mask      = (const float*)d_in[2];
    const float* rot       = (const float*)d_in[3];
    const float* trans     = (const float*)d_in[4];
    const float* rawpw     = (const float*)d_in[5];
    const float* wq_point  = (const float*)d_in[6];
    const float* bq_point  = (const float*)d_in[7];
    const float* wk_point  = (const float*)d_in[8];
    const float* bk_point  = (const float*)d_in[9];
    const float* wv_point  = (const float*)d_in[10];
    const float* bv_point  = (const float*)d_in[11];
    const float* wq_scalar = (const float*)d_in[12];
    const float* wk_scalar = (const float*)d_in[13];
    const float* wv_scalar = (const float*)d_in[14];
    const float* w2d       = (const float*)d_in[15];
    const float* b2d       = (const float*)d_in[16];
    const float* wout      = (const float*)d_in[17];
    const float* bout      = (const float*)d_in[18];
    float* out = (float*)d_out;

    const int smem_logits = (1024 * LPAD + 192) * 4;   // 82688 B
    const int smem_final  = 12288 * 4;                 // 49152 B
    cudaFuncSetAttribute(k_logits, cudaFuncAttributeMaxDynamicSharedMemorySize, smem_logits);
    cudaFuncSetAttribute(k_final,  cudaFuncAttributeMaxDynamicSharedMemorySize, smem_final);

    k_proj<<<dim3(PW / 64, Nn / 64), 256>>>(inputs_1d, wq_point, wk_point, wv_point,
                                            wq_scalar, wk_scalar, wv_scalar,
                                            bq_point, bk_point, bv_point);
    k_rotate<<<Nn, 256>>>(rot, trans);
    k_cheap<<<dim3(16, 8, 12), 256>>>(b2d, rawpw);
    k_logits<<<Nn, 256, smem_logits>>>(inputs_2d, w2d, mask);
    k_av<<<dim3(16, 12), 256>>>();
    k_final<<<Nn, 256, smem_final>>>(inputs_2d);
    k_post<<<Nn, 288>>>(rot, trans);
    k_out<<<dim3(NCHd / 64, Nn / 32), 256>>>(wout, bout, out);
}